// round 3
// baseline (speedup 1.0000x reference)
#include <cuda_runtime.h>

#define NN 100000
#define EE 1600000
#define F  128

// ---------------- device scratch (no allocations allowed) ----------------
__device__ __align__(16) float g_bufA[(size_t)NN * F];   // 51.2 MB
__device__ __align__(16) float g_bufB[(size_t)NN * F];   // 51.2 MB
__device__ float g_dinv[NN];
__device__ int   g_cnt[NN];
__device__ int   g_rowptr[NN + 1];
__device__ int   g_cursor[NN];
__device__ int   g_col[EE];
__device__ int   g_bsums[128];
__device__ int   g_is64;

// read edge index element (handles int32 or int64 storage)
__device__ __forceinline__ int ld_idx(const void* ei, size_t pos) {
    if (g_is64) return (int)((const long long*)ei)[pos];
    return ((const int*)ei)[pos];
}

// ---------------- dtype detect ----------------
// If edge_index is int64 (values < 2^31), every odd 32-bit word of the first
// 2048 words is zero. If int32, those words are src[1],src[3],... (random in
// [0,1e5)), essentially never all zero.
__global__ void k_detect(const int* __restrict__ ei32) {
    __shared__ int nz;
    if (threadIdx.x == 0) nz = 0;
    __syncthreads();
    if (ei32[2 * threadIdx.x + 1] != 0) atomicOr(&nz, 1);
    __syncthreads();
    if (threadIdx.x == 0) g_is64 = (nz == 0) ? 1 : 0;
}

// ---------------- CSR build ----------------
__global__ void k_zero() {
    int i = blockIdx.x * blockDim.x + threadIdx.x;
    if (i < NN) g_cnt[i] = 0;
}

__global__ void k_hist(const void* __restrict__ ei) {
    int e = blockIdx.x * blockDim.x + threadIdx.x;
    if (e < EE) {
        int d = ld_idx(ei, (size_t)EE + e);
        atomicAdd(&g_cnt[d], 1);
    }
}

__global__ void k_dinv() {
    int i = blockIdx.x * blockDim.x + threadIdx.x;
    if (i < NN) g_dinv[i] = rsqrtf((float)(g_cnt[i] + 1));  // +1 self loop
}

__global__ void k_scan1() {
    __shared__ int s[1024];
    int t = threadIdx.x;
    int idx = blockIdx.x * 1024 + t;
    int v = (idx < NN) ? g_cnt[idx] : 0;
    s[t] = v;
    __syncthreads();
    for (int off = 1; off < 1024; off <<= 1) {
        int add = (t >= off) ? s[t - off] : 0;
        __syncthreads();
        s[t] += add;
        __syncthreads();
    }
    if (idx < NN) g_rowptr[idx] = s[t] - v;          // exclusive within block
    if (t == 1023) g_bsums[blockIdx.x] = s[t];       // block total
}

__global__ void k_scan2(int nb) {
    if (threadIdx.x == 0 && blockIdx.x == 0) {
        int run = 0;
        for (int b = 0; b < nb; b++) { int t = g_bsums[b]; g_bsums[b] = run; run += t; }
    }
}

__global__ void k_scan3() {
    int i = blockIdx.x * blockDim.x + threadIdx.x;
    if (i < NN) {
        int v = g_rowptr[i] + g_bsums[i >> 10];
        g_rowptr[i] = v;
        g_cursor[i] = v;
    }
    if (i == 0) g_rowptr[NN] = EE;
}

__global__ void k_fill(const void* __restrict__ ei) {
    int e = blockIdx.x * blockDim.x + threadIdx.x;
    if (e < EE) {
        int d = ld_idx(ei, (size_t)EE + e);
        int s = ld_idx(ei, (size_t)e);
        int p = atomicAdd(&g_cursor[d], 1);
        g_col[p] = s;
    }
}

// ---------------- GEMM: g_bufA[row] = dinv[row] * (in[row] @ W) ----------------
// 256 threads/block, 32 rows/block (4 rows/warp). W held in smem in two
// 64-row halves (32 KB) + X tile (16 KB) = 48 KB static shared.
__global__ void k_gemm(const float* __restrict__ xext, const float* __restrict__ W) {
    __shared__ float sW[64 * F];   // 32 KB (one K-half of W)
    __shared__ float sX[32 * F];   // 16 KB
    const float* in = xext ? xext : g_bufB;
    int tid = threadIdx.x;
    int rowBase = blockIdx.x * 32;
    {
        const float4* a = (const float4*)in;
#pragma unroll
        for (int i = 0; i < 4; i++) {
            int idx = tid + 256 * i;
            int r = rowBase + (idx >> 5);
            float4 v = make_float4(0.f, 0.f, 0.f, 0.f);
            if (r < NN) v = a[(size_t)r * 32 + (idx & 31)];
            ((float4*)sX)[idx] = v;
        }
    }
    int warp = tid >> 5, lane = tid & 31;
    float4 acc[4];
#pragma unroll
    for (int r = 0; r < 4; r++) acc[r] = make_float4(0.f, 0.f, 0.f, 0.f);

    for (int h = 0; h < 2; h++) {
        __syncthreads();   // guards sX (h=0) and prior sW reads (h=1)
        {
            const float4* w4 = (const float4*)(W + h * 64 * F);
#pragma unroll
            for (int i = 0; i < 8; i++) ((float4*)sW)[tid + 256 * i] = w4[tid + 256 * i];
        }
        __syncthreads();
        const float* xr = sX + (warp * 4) * F + h * 64;
#pragma unroll 4
        for (int k = 0; k < 64; k++) {
            float4 wv = ((const float4*)(sW + k * F))[lane];
#pragma unroll
            for (int r = 0; r < 4; r++) {
                float xv = xr[r * F + k];
                acc[r].x = fmaf(xv, wv.x, acc[r].x);
                acc[r].y = fmaf(xv, wv.y, acc[r].y);
                acc[r].z = fmaf(xv, wv.z, acc[r].z);
                acc[r].w = fmaf(xv, wv.w, acc[r].w);
            }
        }
    }
#pragma unroll
    for (int r = 0; r < 4; r++) {
        int row = rowBase + warp * 4 + r;
        if (row < NN) {
            float s = g_dinv[row];
            float4 v = acc[r];
            v.x *= s; v.y *= s; v.z *= s; v.w *= s;
            ((float4*)g_bufA)[(size_t)row * 32 + lane] = v;
        }
    }
}

// ---------------- aggregation: bufB[i] = relu(dinv[i]*(bufA[i] + sum bufA[nbr]) + b) ----------------
// one warp per node, float4 per lane (128 cols)
__global__ void k_agg(const float* __restrict__ bias) {
    int w = (blockIdx.x * blockDim.x + threadIdx.x) >> 5;
    int lane = threadIdx.x & 31;
    if (w >= NN) return;
    const float4* g4 = (const float4*)g_bufA;
    float4 acc = g4[(size_t)w * 32 + lane];   // self loop term
    int s = g_rowptr[w], e = g_rowptr[w + 1];
    for (int p = s; p < e; p++) {
        int j = g_col[p];
        float4 v = g4[(size_t)j * 32 + lane];
        acc.x += v.x; acc.y += v.y; acc.z += v.z; acc.w += v.w;
    }
    float di = g_dinv[w];
    float4 b = ((const float4*)bias)[lane];
    float4 o;
    o.x = fmaxf(fmaf(acc.x, di, b.x), 0.f);
    o.y = fmaxf(fmaf(acc.y, di, b.y), 0.f);
    o.z = fmaxf(fmaf(acc.z, di, b.z), 0.f);
    o.w = fmaxf(fmaf(acc.w, di, b.w), 0.f);
    ((float4*)g_bufB)[(size_t)w * 32 + lane] = o;
}

// ---------------- fused heads (reads g_bufB) ----------------
// pos = relu(h@Wp1+bp1)@Wp2 + bp2 ; time = relu(h@Wt1+bt1)@Wt2 + bt2
// 256 threads/block, 32 rows/block. Weights streamed in K-quarters:
// sX 16KB + sWp 16KB + sWt 8KB = 40 KB static shared.
__global__ void k_head(const float* __restrict__ Wp1, const float* __restrict__ bp1,
                       const float* __restrict__ Wp2, const float* __restrict__ bp2,
                       const float* __restrict__ Wt1, const float* __restrict__ bt1,
                       const float* __restrict__ Wt2, const float* __restrict__ bt2,
                       float* __restrict__ out) {
    __shared__ float sX[32 * F];    // 16 KB
    __shared__ float sWp[32 * F];   // 16 KB (K-quarter of Wp1)
    __shared__ float sWt[32 * 64];  // 8 KB  (K-quarter of Wt1)
    int tid = threadIdx.x;
    int rowBase = blockIdx.x * 32;
    {
        const float4* a = (const float4*)g_bufB;
#pragma unroll
        for (int i = 0; i < 4; i++) {
            int idx = tid + 256 * i;
            int r = rowBase + (idx >> 5);
            float4 v = make_float4(0.f, 0.f, 0.f, 0.f);
            if (r < NN) v = a[(size_t)r * 32 + (idx & 31)];
            ((float4*)sX)[idx] = v;
        }
    }
    int warp = tid >> 5, lane = tid & 31;
    float4 accp[4];
    float2 acct[4];
#pragma unroll
    for (int r = 0; r < 4; r++) {
        accp[r] = make_float4(0.f, 0.f, 0.f, 0.f);
        acct[r] = make_float2(0.f, 0.f);
    }

    for (int q = 0; q < 4; q++) {
        __syncthreads();
        {
            const float4* wp4 = (const float4*)(Wp1 + q * 32 * F);
#pragma unroll
            for (int i = 0; i < 4; i++) ((float4*)sWp)[tid + 256 * i] = wp4[tid + 256 * i];
            const float4* wt4 = (const float4*)(Wt1 + q * 32 * 64);
#pragma unroll
            for (int i = 0; i < 2; i++) ((float4*)sWt)[tid + 256 * i] = wt4[tid + 256 * i];
        }
        __syncthreads();
        const float* xr = sX + (warp * 4) * F + q * 32;
#pragma unroll 4
        for (int k = 0; k < 32; k++) {
            float4 wp = ((const float4*)(sWp + k * F))[lane];
            float2 wt = ((const float2*)(sWt + k * 64))[lane];
#pragma unroll
            for (int r = 0; r < 4; r++) {
                float xv = xr[r * F + k];
                accp[r].x = fmaf(xv, wp.x, accp[r].x);
                accp[r].y = fmaf(xv, wp.y, accp[r].y);
                accp[r].z = fmaf(xv, wp.z, accp[r].z);
                accp[r].w = fmaf(xv, wp.w, accp[r].w);
                acct[r].x = fmaf(xv, wt.x, acct[r].x);
                acct[r].y = fmaf(xv, wt.y, acct[r].y);
            }
        }
    }

    // epilogue: per-lane second-layer weights, warp reduce
    float4 bP = ((const float4*)bp1)[lane];
    float2 bT = ((const float2*)bt1)[lane];
    float wp2a[4], wp2b[4];
#pragma unroll
    for (int i = 0; i < 4; i++) {
        wp2a[i] = Wp2[(lane * 4 + i) * 2];
        wp2b[i] = Wp2[(lane * 4 + i) * 2 + 1];
    }
    float wt2_0 = Wt2[lane * 2], wt2_1 = Wt2[lane * 2 + 1];
    float bpos0 = bp2[0], bpos1 = bp2[1], btime = bt2[0];

#pragma unroll
    for (int r = 0; r < 4; r++) {
        int row = rowBase + warp * 4 + r;
        float p0 = fmaxf(accp[r].x + bP.x, 0.f);
        float p1 = fmaxf(accp[r].y + bP.y, 0.f);
        float p2 = fmaxf(accp[r].z + bP.z, 0.f);
        float p3 = fmaxf(accp[r].w + bP.w, 0.f);
        float t0 = fmaxf(acct[r].x + bT.x, 0.f);
        float t1 = fmaxf(acct[r].y + bT.y, 0.f);
        float px = p0 * wp2a[0] + p1 * wp2a[1] + p2 * wp2a[2] + p3 * wp2a[3];
        float py = p0 * wp2b[0] + p1 * wp2b[1] + p2 * wp2b[2] + p3 * wp2b[3];
        float tv = t0 * wt2_0 + t1 * wt2_1;
#pragma unroll
        for (int off = 16; off; off >>= 1) {
            px += __shfl_down_sync(0xffffffffu, px, off);
            py += __shfl_down_sync(0xffffffffu, py, off);
            tv += __shfl_down_sync(0xffffffffu, tv, off);
        }
        if (lane == 0 && row < NN) {
            out[(size_t)row * 3 + 0] = px + bpos0;
            out[(size_t)row * 3 + 1] = py + bpos1;
            out[(size_t)row * 3 + 2] = tv + btime;
        }
    }
}

// ---------------- launch ----------------
extern "C" void kernel_launch(void* const* d_in, const int* in_sizes, int n_in,
                              void* d_out, int out_size) {
    const float* x   = (const float*)d_in[0];
    const void*  ei  = d_in[1];
    const float* W1  = (const float*)d_in[2];  const float* b1  = (const float*)d_in[3];
    const float* W2  = (const float*)d_in[4];  const float* b2  = (const float*)d_in[5];
    const float* W3  = (const float*)d_in[6];  const float* b3  = (const float*)d_in[7];
    const float* Wp1 = (const float*)d_in[8];  const float* bp1 = (const float*)d_in[9];
    const float* Wp2 = (const float*)d_in[10]; const float* bp2 = (const float*)d_in[11];
    const float* Wt1 = (const float*)d_in[12]; const float* bt1 = (const float*)d_in[13];
    const float* Wt2 = (const float*)d_in[14]; const float* bt2 = (const float*)d_in[15];
    float* out = (float*)d_out;

    int nb256  = (NN + 255) / 256;
    int ebl    = (EE + 255) / 256;
    int nbScan = (NN + 1023) / 1024;

    k_detect<<<1, 1024>>>((const int*)ei);
    k_zero<<<nb256, 256>>>();
    k_hist<<<ebl, 256>>>(ei);
    k_dinv<<<nb256, 256>>>();
    k_scan1<<<nbScan, 1024>>>();
    k_scan2<<<1, 1>>>(nbScan);
    k_scan3<<<nb256, 256>>>();
    k_fill<<<ebl, 256>>>(ei);

    int gemmGrid = (NN + 31) / 32;
    int aggGrid  = (NN + 7) / 8;   // 8 warps per 256-thread block, 1 warp per node

    k_gemm<<<gemmGrid, 256>>>(x, W1);
    k_agg <<<aggGrid, 256>>>(b1);
    k_gemm<<<gemmGrid, 256>>>(nullptr, W2);
    k_agg <<<aggGrid, 256>>>(b2);
    k_gemm<<<gemmGrid, 256>>>(nullptr, W3);
    k_agg <<<aggGrid, 256>>>(b3);

    k_head<<<gemmGrid, 256>>>(Wp1, bp1, Wp2, bp2, Wt1, bt1, Wt2, bt2, out);
}